// round 1
// baseline (speedup 1.0000x reference)
#include <cuda_runtime.h>
#include <cuda_bf16.h>

#define Bq 16
#define Nq 1024
#define FIN 64
#define FOUT 128
#define DQ 64
#define HQ 4
#define NEG_SLOPE 0.2f

#define OUT_ELEMS (Bq*Nq*FOUT)          // 2097152
#define ATTN_ELEMS ((long)Bq*HQ*Nq*Nq)  // 67108864

// Scratch (static device globals — allowed; no runtime allocation)
__device__ float g_hp[Bq*HQ*Nq*FOUT];    // h_prime [B,H,N,128]  33.5 MB
__device__ float g_src[Bq*HQ*Nq*DQ];     // attn_src [B,H,N,64]  16.8 MB
__device__ float g_dst[Bq*HQ*Nq*DQ];     // attn_dst [B,H,N,64]  16.8 MB

// -------------------------------------------------------------------------
// K1: h_prime = h @ w[h]  (per b,h; 16 n-rows per block, 128 threads = one o each)
//     then fused attn_src/attn_dst = h_prime @ a_src/a_dst
// -------------------------------------------------------------------------
__global__ void k1_hprime_proj(const float* __restrict__ h,
                               const float* __restrict__ w,
                               const float* __restrict__ a_src,
                               const float* __restrict__ a_dst) {
    __shared__ float h_s[16*FIN];       // 4 KB
    __shared__ float w_s[FIN*FOUT];     // 32 KB (reused as hp tile in phase 2)

    const int hh = blockIdx.y;
    const int b  = blockIdx.z;
    const int n0 = blockIdx.x * 16;
    const int tid = threadIdx.x;        // 128

    // load 16 rows of h and the full weight for this head
    const float* hrow = h + ((long)b*Nq + n0)*FIN;
    for (int i = tid; i < 16*FIN; i += 128) h_s[i] = hrow[i];
    const float* wp = w + hh*FIN*FOUT;
    for (int i = tid; i < FIN*FOUT; i += 128) w_s[i] = wp[i];
    __syncthreads();

    float acc[16];
#pragma unroll
    for (int r = 0; r < 16; r++) acc[r] = 0.f;
#pragma unroll
    for (int f = 0; f < FIN; f++) {
        float wv = w_s[f*FOUT + tid];
#pragma unroll
        for (int r = 0; r < 16; r++) acc[r] += h_s[r*FIN + f] * wv;
    }

    // write h_prime
    float* hp = g_hp + (((long)(b*HQ + hh))*Nq + n0)*FOUT;
#pragma unroll
    for (int r = 0; r < 16; r++) hp[r*FOUT + tid] = acc[r];

    // stash h_prime tile in smem (reuse w_s) for the projections
    __syncthreads();
#pragma unroll
    for (int r = 0; r < 16; r++) w_s[r*FOUT + tid] = acc[r];
    __syncthreads();

    // phase 2: tid<64 -> attn_src[d=tid], tid>=64 -> attn_dst[d=tid-64]
    const int d = tid & 63;
    const float* ap = ((tid < 64) ? a_src : a_dst) + hh*FOUT*DQ;
    float sacc[16];
#pragma unroll
    for (int r = 0; r < 16; r++) sacc[r] = 0.f;
    for (int o = 0; o < FOUT; o++) {
        float av = ap[o*DQ + d];                 // coalesced over d, L2-resident
#pragma unroll
        for (int r = 0; r < 16; r++) sacc[r] += w_s[r*FOUT + o] * av;
    }
    float* op = ((tid < 64) ? g_src : g_dst) + (((long)(b*HQ + hh))*Nq + n0)*DQ;
#pragma unroll
    for (int r = 0; r < 16; r++) op[r*DQ + d] = sacc[r];
}

// -------------------------------------------------------------------------
// K3: scores = attn_src @ attn_dst^T, leaky-relu, softmax over m, * mask,
//     writes attn straight into d_out attn region.
//     Block: 8 n-rows (one per warp), 256 threads. 32 scores per lane.
// -------------------------------------------------------------------------
__global__ void k3_scores_softmax(const float* __restrict__ mask,
                                  float* __restrict__ attn_out) {
    __shared__ float src_s[8*DQ];        // 2 KB
    __shared__ float dst_s[128*65];      // 33.3 KB, padded stride 65 -> conflict-free

    const int b  = blockIdx.z;
    const int hh = blockIdx.y;
    const int n0 = blockIdx.x * 8;
    const int tid = threadIdx.x;         // 256
    const int warp = tid >> 5, lane = tid & 31;

    const float* srcp = g_src + (((long)(b*HQ + hh))*Nq + n0)*DQ;
    for (int i = tid; i < 8*DQ; i += 256) src_s[i] = srcp[i];
    const float* dstb = g_dst + ((long)(b*HQ + hh))*Nq*DQ;

    float sc[32];
    for (int t = 0; t < 8; t++) {
        __syncthreads();
        const float* dp = dstb + t*128*DQ;
        for (int i = tid; i < 128*DQ; i += 256) {
            int m = i >> 6, d = i & 63;
            dst_s[m*65 + d] = dp[i];
        }
        __syncthreads();
        float a0 = 0.f, a1 = 0.f, a2 = 0.f, a3 = 0.f;
        const float* sr = src_s + warp*DQ;
#pragma unroll
        for (int d = 0; d < DQ; d++) {
            float s = sr[d];
            a0 += s * dst_s[(lane      )*65 + d];
            a1 += s * dst_s[(lane + 32 )*65 + d];
            a2 += s * dst_s[(lane + 64 )*65 + d];
            a3 += s * dst_s[(lane + 96 )*65 + d];
        }
        sc[t*4+0] = a0; sc[t*4+1] = a1; sc[t*4+2] = a2; sc[t*4+3] = a3;
    }

    // leaky relu
#pragma unroll
    for (int k = 0; k < 32; k++) {
        float s = sc[k];
        sc[k] = s > 0.f ? s : NEG_SLOPE * s;
    }
    // row max (lane-local 32 values + warp reduce)
    float mx = -3.4e38f;
#pragma unroll
    for (int k = 0; k < 32; k++) mx = fmaxf(mx, sc[k]);
#pragma unroll
    for (int off = 16; off; off >>= 1) mx = fmaxf(mx, __shfl_xor_sync(0xffffffffu, mx, off));
    // exp + sum
    float sum = 0.f;
#pragma unroll
    for (int k = 0; k < 32; k++) { sc[k] = __expf(sc[k] - mx); sum += sc[k]; }
#pragma unroll
    for (int off = 16; off; off >>= 1) sum += __shfl_xor_sync(0xffffffffu, sum, off);
    const float inv = 1.f / sum;

    const int n = n0 + warp;
    const float* mrow = mask + ((long)b*Nq + n)*Nq;
    float* arow = attn_out + (((long)(b*HQ + hh))*Nq + n)*(long)Nq;
#pragma unroll
    for (int t = 0; t < 8; t++)
#pragma unroll
        for (int g = 0; g < 4; g++) {
            int m = t*128 + g*32 + lane;
            arow[m] = sc[t*4+g] * inv * mrow[m];
        }
}

// -------------------------------------------------------------------------
// K4: out[b,n,:] = sum_h attn[b,h,n,:] @ h_prime[b,h,:,:] + bias + sum_h h_prime[b,h,n,:]
//     Block tile 64 n-rows x 128 cols, k-tile 32, 256 threads, 8x4 micro-tile.
// -------------------------------------------------------------------------
__global__ void k4_pv_out(const float* __restrict__ bias,
                          const float* __restrict__ attn,
                          float* __restrict__ out) {
    __shared__ float attn_s[64*33];   // 8.4 KB, pad 33
    __shared__ float hp_s[32*FOUT];   // 16 KB, float4-read

    const int b  = blockIdx.y;
    const int n0 = blockIdx.x * 64;
    const int tid = threadIdx.x;      // 256
    const int tx = tid & 31;          // col group: o = tx*4 .. tx*4+3
    const int ty = tid >> 5;          // rows n0 + ty + 8k, k=0..7

    float acc[8][4];
#pragma unroll
    for (int k = 0; k < 8; k++)
#pragma unroll
        for (int i = 0; i < 4; i++) acc[k][i] = 0.f;

    for (int hh = 0; hh < HQ; hh++) {
        const float* abase = attn + (((long)(b*HQ + hh))*Nq + n0)*(long)Nq;
        const float* hpb   = g_hp + ((long)(b*HQ + hh))*Nq*FOUT;
        for (int mt = 0; mt < Nq/32; mt++) {
            __syncthreads();
            for (int i = tid; i < 64*32; i += 256) {
                int r = i >> 5, c = i & 31;
                attn_s[r*33 + c] = abase[(long)r*Nq + mt*32 + c];
            }
            const float* hpt = hpb + mt*32*FOUT;
            for (int i = tid; i < 32*FOUT; i += 256) hp_s[i] = hpt[i];
            __syncthreads();
#pragma unroll
            for (int m = 0; m < 32; m++) {
                float4 bv = *(const float4*)&hp_s[m*FOUT + tx*4];
#pragma unroll
                for (int k = 0; k < 8; k++) {
                    float av = attn_s[(ty + 8*k)*33 + m];
                    acc[k][0] += av * bv.x;
                    acc[k][1] += av * bv.y;
                    acc[k][2] += av * bv.z;
                    acc[k][3] += av * bv.w;
                }
            }
        }
    }

    // epilogue: bias + skip (sum over heads of h_prime)
    const float4 bi = *(const float4*)&bias[tx*4];
#pragma unroll
    for (int k = 0; k < 8; k++) {
        const int n = n0 + ty + 8*k;
        float4 sk = make_float4(0.f, 0.f, 0.f, 0.f);
#pragma unroll
        for (int hh = 0; hh < HQ; hh++) {
            const float4 hv = *(const float4*)&g_hp[((((long)(b*HQ + hh))*Nq + n)*FOUT) + tx*4];
            sk.x += hv.x; sk.y += hv.y; sk.z += hv.z; sk.w += hv.w;
        }
        float4 ov;
        ov.x = acc[k][0] + bi.x + sk.x;
        ov.y = acc[k][1] + bi.y + sk.y;
        ov.z = acc[k][2] + bi.z + sk.z;
        ov.w = acc[k][3] + bi.w + sk.w;
        *(float4*)&out[(((long)b*Nq + n)*FOUT) + tx*4] = ov;
    }
}

extern "C" void kernel_launch(void* const* d_in, const int* in_sizes, int n_in,
                              void* d_out, int out_size) {
    const float* h     = (const float*)d_in[0];
    const float* mask  = (const float*)d_in[1];
    const float* w     = (const float*)d_in[2];
    const float* a_src = (const float*)d_in[3];
    const float* a_dst = (const float*)d_in[4];
    const float* bias  = (const float*)d_in[5];

    float* out      = (float*)d_out;               // [B,N,128]
    float* attn_out = (float*)d_out + OUT_ELEMS;   // [B,H,N,N]

    // K1: h_prime + projections
    k1_hprime_proj<<<dim3(Nq/16, HQ, Bq), 128>>>(h, w, a_src, a_dst);
    // K3: scores + softmax + mask -> attn region of d_out
    k3_scores_softmax<<<dim3(Nq/8, HQ, Bq), 256>>>(mask, attn_out);
    // K4: PV + bias + skip -> out region of d_out
    k4_pv_out<<<dim3(Nq/64, Bq), 256>>>(bias, attn_out, out);
}

// round 2
// speedup vs baseline: 1.9089x; 1.9089x over previous
#include <cuda_runtime.h>
#include <cuda_bf16.h>
#include <cstdint>

#define Bq 16
#define Nq 1024
#define FIN 64
#define FOUT 128
#define DQ 64
#define HQ 4
#define NEG_SLOPE 0.2f

#define OUT_ELEMS (Bq*Nq*FOUT)          // 2097152

// Scratch (static device globals — allowed; no runtime allocation)
__device__ float g_hp[Bq*HQ*Nq*FOUT];        // h_prime [B,H,N,128]
__device__ float g_src[Bq*HQ*Nq*DQ];         // attn_src [B,H,N,64]
__device__ float g_dst[Bq*HQ*Nq*DQ];         // attn_dst [B,H,N,64]
__device__ float g_sc[(size_t)Bq*HQ*Nq*Nq];  // raw scores [B,H,N,N] 268MB

// ---------------- tf32 helpers ----------------
__device__ __forceinline__ uint32_t f2tf(float f) {
    uint32_t r; asm("cvt.rna.tf32.f32 %0, %1;" : "=r"(r) : "f"(f)); return r;
}
__device__ __forceinline__ void mma8(float* c,
                                     uint32_t a0, uint32_t a1, uint32_t a2, uint32_t a3,
                                     uint32_t b0, uint32_t b1) {
    asm("mma.sync.aligned.m16n8k8.row.col.f32.tf32.tf32.f32 "
        "{%0,%1,%2,%3}, {%4,%5,%6,%7}, {%8,%9}, {%0,%1,%2,%3};"
        : "+f"(c[0]), "+f"(c[1]), "+f"(c[2]), "+f"(c[3])
        : "r"(a0), "r"(a1), "r"(a2), "r"(a3), "r"(b0), "r"(b1));
}

// -------------------------------------------------------------------------
// K1: h_prime = h @ w[h], then attn_src/attn_dst = h_prime @ a_src/a_dst
// -------------------------------------------------------------------------
__global__ void k1_hprime_proj(const float* __restrict__ h,
                               const float* __restrict__ w,
                               const float* __restrict__ a_src,
                               const float* __restrict__ a_dst) {
    __shared__ float h_s[16*FIN];
    __shared__ float w_s[FIN*FOUT];

    const int hh = blockIdx.y;
    const int b  = blockIdx.z;
    const int n0 = blockIdx.x * 16;
    const int tid = threadIdx.x;        // 128

    const float* hrow = h + ((long)b*Nq + n0)*FIN;
    for (int i = tid; i < 16*FIN; i += 128) h_s[i] = hrow[i];
    const float* wp = w + hh*FIN*FOUT;
    for (int i = tid; i < FIN*FOUT; i += 128) w_s[i] = wp[i];
    __syncthreads();

    float acc[16];
#pragma unroll
    for (int r = 0; r < 16; r++) acc[r] = 0.f;
#pragma unroll
    for (int f = 0; f < FIN; f++) {
        float wv = w_s[f*FOUT + tid];
#pragma unroll
        for (int r = 0; r < 16; r++) acc[r] += h_s[r*FIN + f] * wv;
    }

    float* hp = g_hp + (((long)(b*HQ + hh))*Nq + n0)*FOUT;
#pragma unroll
    for (int r = 0; r < 16; r++) hp[r*FOUT + tid] = acc[r];

    __syncthreads();
#pragma unroll
    for (int r = 0; r < 16; r++) w_s[r*FOUT + tid] = acc[r];
    __syncthreads();

    const int d = tid & 63;
    const float* ap = ((tid < 64) ? a_src : a_dst) + hh*FOUT*DQ;
    float sacc[16];
#pragma unroll
    for (int r = 0; r < 16; r++) sacc[r] = 0.f;
    for (int o = 0; o < FOUT; o++) {
        float av = ap[o*DQ + d];
#pragma unroll
        for (int r = 0; r < 16; r++) sacc[r] += w_s[r*FOUT + o] * av;
    }
    float* op = ((tid < 64) ? g_src : g_dst) + (((long)(b*HQ + hh))*Nq + n0)*DQ;
#pragma unroll
    for (int r = 0; r < 16; r++) op[r*DQ + d] = sacc[r];
}

// -------------------------------------------------------------------------
// K3: raw scores = attn_src @ attn_dst^T via 3xTF32 mma. 64x64 block tile.
// 256 threads = 8 warps in 4x2; warp tile 16 rows x 32 cols.
// -------------------------------------------------------------------------
#define K3_STR 68
__global__ __launch_bounds__(256) void k3_scores() {
    __shared__ float As[64*K3_STR];   // src tile  [64 rows][64 k] stride 68
    __shared__ float Bs[64*K3_STR];   // dst tile  [64 cols][64 k]

    const int m0 = blockIdx.x * 64;
    const int n0 = blockIdx.y * 64;
    const int bh = blockIdx.z;
    const int tid = threadIdx.x;

    const float* srcp = g_src + ((long)bh*Nq + n0)*DQ;
    const float* dstp = g_dst + ((long)bh*Nq + m0)*DQ;
#pragma unroll
    for (int t = 0; t < 4; t++) {
        int j = tid + t*256;          // 0..1023 float4s
        int r = j >> 4, c = (j & 15) * 4;
        *(float4*)&As[r*K3_STR + c] = *(const float4*)&srcp[r*DQ + c];
        *(float4*)&Bs[r*K3_STR + c] = *(const float4*)&dstp[r*DQ + c];
    }
    __syncthreads();

    const int warp = tid >> 5, lane = tid & 31;
    const int wr = warp >> 1;         // 0..3 -> row offset *16
    const int wc = warp & 1;          // 0..1 -> col offset *32
    const int qr = lane >> 2, qk = lane & 3;

    float C[4][4];
#pragma unroll
    for (int i = 0; i < 4; i++)
#pragma unroll
        for (int j = 0; j < 4; j++) C[i][j] = 0.f;

#pragma unroll
    for (int kk = 0; kk < 8; kk++) {
        const int k0 = kk*8;
        const float* apt = &As[(wr*16 + qr)*K3_STR + k0 + qk];
        float a0 = apt[0], a1 = apt[8*K3_STR], a2 = apt[4], a3 = apt[8*K3_STR + 4];
        uint32_t ah0 = f2tf(a0), ah1 = f2tf(a1), ah2 = f2tf(a2), ah3 = f2tf(a3);
        uint32_t al0 = f2tf(a0 - __uint_as_float(ah0));
        uint32_t al1 = f2tf(a1 - __uint_as_float(ah1));
        uint32_t al2 = f2tf(a2 - __uint_as_float(ah2));
        uint32_t al3 = f2tf(a3 - __uint_as_float(ah3));
#pragma unroll
        for (int ct = 0; ct < 4; ct++) {
            const float* bpt = &Bs[(wc*32 + ct*8 + qr)*K3_STR + k0 + qk];
            float b0 = bpt[0], b1 = bpt[4];
            uint32_t bh0 = f2tf(b0), bh1 = f2tf(b1);
            uint32_t bl0 = f2tf(b0 - __uint_as_float(bh0));
            uint32_t bl1 = f2tf(b1 - __uint_as_float(bh1));
            mma8(C[ct], ah0, ah1, ah2, ah3, bh0, bh1);
            mma8(C[ct], al0, al1, al2, al3, bh0, bh1);
            mma8(C[ct], ah0, ah1, ah2, ah3, bl0, bl1);
        }
    }

    float* op = g_sc + ((size_t)bh*Nq + n0 + wr*16 + qr)*Nq + m0 + wc*32 + qk*2;
#pragma unroll
    for (int ct = 0; ct < 4; ct++) {
        *(float2*)&op[ct*8]                  = make_float2(C[ct][0], C[ct][1]);
        *(float2*)&op[(size_t)8*Nq + ct*8]   = make_float2(C[ct][2], C[ct][3]);
    }
}

// -------------------------------------------------------------------------
// K3b: leaky-relu + softmax + mask. One warp per row.
// -------------------------------------------------------------------------
__global__ __launch_bounds__(256) void k3b_softmax(const float* __restrict__ mask,
                                                   float* __restrict__ attn_out) {
    const int warp = threadIdx.x >> 5, lane = threadIdx.x & 31;
    const long row = (long)blockIdx.x*8 + warp;      // [0, B*H*N)
    const int n  = (int)(row & (Nq - 1));
    const int bh = (int)(row >> 10);
    const int b  = bh >> 2;

    const float4* sp = (const float4*)(g_sc + (size_t)row*Nq);
    float4 v[8];
    float mx = -3.4e38f;
#pragma unroll
    for (int t = 0; t < 8; t++) {
        float4 x = sp[lane + t*32];
        x.x = x.x > 0.f ? x.x : NEG_SLOPE*x.x;
        x.y = x.y > 0.f ? x.y : NEG_SLOPE*x.y;
        x.z = x.z > 0.f ? x.z : NEG_SLOPE*x.z;
        x.w = x.w > 0.f ? x.w : NEG_SLOPE*x.w;
        v[t] = x;
        mx = fmaxf(mx, fmaxf(fmaxf(x.x, x.y), fmaxf(x.z, x.w)));
    }
#pragma unroll
    for (int o = 16; o; o >>= 1) mx = fmaxf(mx, __shfl_xor_sync(0xffffffffu, mx, o));
    float sum = 0.f;
#pragma unroll
    for (int t = 0; t < 8; t++) {
        v[t].x = __expf(v[t].x - mx);
        v[t].y = __expf(v[t].y - mx);
        v[t].z = __expf(v[t].z - mx);
        v[t].w = __expf(v[t].w - mx);
        sum += (v[t].x + v[t].y) + (v[t].z + v[t].w);
    }
#pragma unroll
    for (int o = 16; o; o >>= 1) sum += __shfl_xor_sync(0xffffffffu, sum, o);
    const float inv = 1.f / sum;

    const float4* mp = (const float4*)(mask + ((long)b*Nq + n)*Nq);
    float4* op = (float4*)(attn_out + (size_t)row*Nq);
#pragma unroll
    for (int t = 0; t < 8; t++) {
        float4 m = mp[lane + t*32];
        float4 x = v[t];
        op[lane + t*32] = make_float4(x.x*inv*m.x, x.y*inv*m.y, x.z*inv*m.z, x.w*inv*m.w);
    }
}

// -------------------------------------------------------------------------
// K4: out = sum_h attn @ h_prime + bias + sum_h h_prime, via 3xTF32 mma.
// Block tile 64 rows x 128 cols; 8 warps in 2x4; warp tile 32x32. k-chunk 32.
// -------------------------------------------------------------------------
#define A4_STR 36
#define B4_STR 136
__global__ __launch_bounds__(256) void k4_pv(const float* __restrict__ bias,
                                             const float* __restrict__ attn,
                                             float* __restrict__ out) {
    __shared__ float As[64*A4_STR];    // attn tile [64 rows][32 k]
    __shared__ float Bs[32*B4_STR];    // hp tile   [32 k][128 cols]

    const int b  = blockIdx.y;
    const int n0 = blockIdx.x * 64;
    const int tid = threadIdx.x;
    const int warp = tid >> 5, lane = tid & 31;
    const int wr = warp >> 2;          // 0..1 -> row offset *32
    const int wc = warp & 3;           // 0..3 -> col offset *32
    const int qr = lane >> 2, qk = lane & 3;

    float C[2][4][4];
#pragma unroll
    for (int i = 0; i < 2; i++)
#pragma unroll
        for (int j = 0; j < 4; j++)
#pragma unroll
            for (int k = 0; k < 4; k++) C[i][j][k] = 0.f;

    for (int hh = 0; hh < HQ; hh++) {
        const float* ab = attn + (((size_t)(b*HQ + hh))*Nq + n0)*Nq;
        const float* hb = g_hp + ((long)(b*HQ + hh))*Nq*FOUT;
        for (int kt = 0; kt < Nq/32; kt++) {
            __syncthreads();
#pragma unroll
            for (int t = 0; t < 2; t++) {
                int j = tid + t*256;   // 0..511: 64 rows x 8 f4
                int r = j >> 3, c = (j & 7) * 4;
                *(float4*)&As[r*A4_STR + c] = *(const float4*)&ab[(size_t)r*Nq + kt*32 + c];
            }
#pragma unroll
            for (int t = 0; t < 4; t++) {
                int j = tid + t*256;   // 0..1023: 32 rows x 32 f4
                int r = j >> 5, c = (j & 31) * 4;
                *(float4*)&Bs[r*B4_STR + c] = *(const float4*)&hb[(long)(kt*32 + r)*FOUT + c];
            }
            __syncthreads();
#pragma unroll
            for (int kk = 0; kk < 4; kk++) {
                const int k0 = kk*8;
                uint32_t AH[2][4], AL[2][4];
#pragma unroll
                for (int rt = 0; rt < 2; rt++) {
                    const float* apt = &As[(wr*32 + rt*16 + qr)*A4_STR + k0 + qk];
                    float a0 = apt[0], a1 = apt[8*A4_STR], a2 = apt[4], a3 = apt[8*A4_STR + 4];
                    AH[rt][0] = f2tf(a0); AL[rt][0] = f2tf(a0 - __uint_as_float(AH[rt][0]));
                    AH[rt][1] = f2tf(a1); AL[rt][1] = f2tf(a1 - __uint_as_float(AH[rt][1]));
                    AH[rt][2] = f2tf(a2); AL[rt][2] = f2tf(a2 - __uint_as_float(AH[rt][2]));
                    AH[rt][3] = f2tf(a3); AL[rt][3] = f2tf(a3 - __uint_as_float(AH[rt][3]));
                }
#pragma unroll
                for (int ct = 0; ct < 4; ct++) {
                    const float* bpt = &Bs[(k0 + qk)*B4_STR + wc*32 + ct*8 + qr];
                    float b0 = bpt[0], b1 = bpt[4*B4_STR];
                    uint32_t bh0 = f2tf(b0), bh1 = f2tf(b1);
                    uint32_t bl0 = f2tf(b0 - __uint_as_float(bh0));
                    uint32_t bl1 = f2tf(b1 - __uint_as_float(bh1));
#pragma unroll
                    for (int rt = 0; rt < 2; rt++) {
                        mma8(C[rt][ct], AH[rt][0], AH[rt][1], AH[rt][2], AH[rt][3], bh0, bh1);
                        mma8(C[rt][ct], AL[rt][0], AL[rt][1], AL[rt][2], AL[rt][3], bh0, bh1);
                        mma8(C[rt][ct], AH[rt][0], AH[rt][1], AH[rt][2], AH[rt][3], bl0, bl1);
                    }
                }
            }
        }
    }

    // epilogue: bias + skip (sum over heads of h_prime)
#pragma unroll
    for (int rt = 0; rt < 2; rt++) {
#pragma unroll
        for (int ct = 0; ct < 4; ct++) {
            int row = n0 + wr*32 + rt*16 + qr;
            int col = wc*32 + ct*8 + qk*2;
            float2 sk0 = make_float2(0.f, 0.f), sk1 = make_float2(0.f, 0.f);
#pragma unroll
            for (int hh = 0; hh < HQ; hh++) {
                const float* hb = g_hp + ((long)(b*HQ + hh))*Nq*FOUT;
                float2 x0 = *(const float2*)&hb[(long)row*FOUT + col];
                float2 x1 = *(const float2*)&hb[(long)(row + 8)*FOUT + col];
                sk0.x += x0.x; sk0.y += x0.y;
                sk1.x += x1.x; sk1.y += x1.y;
            }
            float2 bi = *(const float2*)&bias[col];
            *(float2*)&out[((long)b*Nq + row)*FOUT + col] =
                make_float2(C[rt][ct][0] + bi.x + sk0.x, C[rt][ct][1] + bi.y + sk0.y);
            *(float2*)&out[((long)b*Nq + row + 8)*FOUT + col] =
                make_float2(C[rt][ct][2] + bi.x + sk1.x, C[rt][ct][3] + bi.y + sk1.y);
        }
    }
}

extern "C" void kernel_launch(void* const* d_in, const int* in_sizes, int n_in,
                              void* d_out, int out_size) {
    const float* h     = (const float*)d_in[0];
    const float* mask  = (const float*)d_in[1];
    const float* w     = (const float*)d_in[2];
    const float* a_src = (const float*)d_in[3];
    const float* a_dst = (const float*)d_in[4];
    const float* bias  = (const float*)d_in[5];

    float* out      = (float*)d_out;               // [B,N,128]
    float* attn_out = (float*)d_out + OUT_ELEMS;   // [B,H,N,N]

    k1_hprime_proj<<<dim3(Nq/16, HQ, Bq), 128>>>(h, w, a_src, a_dst);
    k3_scores<<<dim3(Nq/64, Nq/64, Bq*HQ), 256>>>();
    k3b_softmax<<<(Bq*HQ*Nq)/8, 256>>>(mask, attn_out);
    k4_pv<<<dim3(Nq/64, Bq), 256>>>(bias, attn_out, out);
}

// round 3
// speedup vs baseline: 1.9188x; 1.0052x over previous
#include <cuda_runtime.h>
#include <cuda_bf16.h>
#include <cstdint>

#define Bq 16
#define Nq 1024
#define FIN 64
#define FOUT 128
#define DQ 64
#define HQ 4
#define NEG_SLOPE 0.2f

#define OUT_ELEMS (Bq*Nq*FOUT)          // 2097152

// Scratch (static device globals — allowed; no runtime allocation)
__device__ float    g_hp[Bq*HQ*Nq*FOUT];        // h_prime fp32 (for skip epilogue)
__device__ uint32_t g_hp_hi[Bq*HQ*Nq*FOUT];     // h_prime tf32 hi
__device__ uint32_t g_hp_lo[Bq*HQ*Nq*FOUT];     // h_prime tf32 lo
__device__ uint32_t g_src_hi[Bq*HQ*Nq*DQ];
__device__ uint32_t g_src_lo[Bq*HQ*Nq*DQ];
__device__ uint32_t g_dst_hi[Bq*HQ*Nq*DQ];
__device__ uint32_t g_dst_lo[Bq*HQ*Nq*DQ];
__device__ float    g_sc[(size_t)Bq*HQ*Nq*Nq];  // raw scores [B,H,N,N]

// ---------------- tf32 helpers ----------------
__device__ __forceinline__ uint32_t f2tf(float f) {
    uint32_t r; asm("cvt.rna.tf32.f32 %0, %1;" : "=r"(r) : "f"(f)); return r;
}
__device__ __forceinline__ void mma8(float* c,
                                     uint32_t a0, uint32_t a1, uint32_t a2, uint32_t a3,
                                     uint32_t b0, uint32_t b1) {
    asm("mma.sync.aligned.m16n8k8.row.col.f32.tf32.tf32.f32 "
        "{%0,%1,%2,%3}, {%4,%5,%6,%7}, {%8,%9}, {%0,%1,%2,%3};"
        : "+f"(c[0]), "+f"(c[1]), "+f"(c[2]), "+f"(c[3])
        : "r"(a0), "r"(a1), "r"(a2), "r"(a3), "r"(b0), "r"(b1));
}

// -------------------------------------------------------------------------
// K1: h_prime = h @ w[h]; attn_src/dst = h_prime @ a_src/a_dst.
// Also emits tf32 hi/lo splits of h_prime, attn_src, attn_dst.
// -------------------------------------------------------------------------
__global__ void k1_hprime_proj(const float* __restrict__ h,
                               const float* __restrict__ w,
                               const float* __restrict__ a_src,
                               const float* __restrict__ a_dst) {
    __shared__ float h_s[16*FIN];
    __shared__ float w_s[FIN*FOUT];

    const int hh = blockIdx.y;
    const int b  = blockIdx.z;
    const int n0 = blockIdx.x * 16;
    const int tid = threadIdx.x;        // 128

    const float* hrow = h + ((long)b*Nq + n0)*FIN;
    for (int i = tid; i < 16*FIN; i += 128) h_s[i] = hrow[i];
    const float* wp = w + hh*FIN*FOUT;
    for (int i = tid; i < FIN*FOUT; i += 128) w_s[i] = wp[i];
    __syncthreads();

    float acc[16];
#pragma unroll
    for (int r = 0; r < 16; r++) acc[r] = 0.f;
#pragma unroll
    for (int f = 0; f < FIN; f++) {
        float wv = w_s[f*FOUT + tid];
#pragma unroll
        for (int r = 0; r < 16; r++) acc[r] += h_s[r*FIN + f] * wv;
    }

    const long hbase = (((long)(b*HQ + hh))*Nq + n0)*FOUT;
#pragma unroll
    for (int r = 0; r < 16; r++) {
        float v = acc[r];
        uint32_t hi = f2tf(v);
        g_hp[hbase + r*FOUT + tid]    = v;
        g_hp_hi[hbase + r*FOUT + tid] = hi;
        g_hp_lo[hbase + r*FOUT + tid] = f2tf(v - __uint_as_float(hi));
    }

    __syncthreads();
#pragma unroll
    for (int r = 0; r < 16; r++) w_s[r*FOUT + tid] = acc[r];
    __syncthreads();

    const int d = tid & 63;
    const float* ap = ((tid < 64) ? a_src : a_dst) + hh*FOUT*DQ;
    float sacc[16];
#pragma unroll
    for (int r = 0; r < 16; r++) sacc[r] = 0.f;
    for (int o = 0; o < FOUT; o++) {
        float av = ap[o*DQ + d];
#pragma unroll
        for (int r = 0; r < 16; r++) sacc[r] += w_s[r*FOUT + o] * av;
    }
    uint32_t* oh = ((tid < 64) ? g_src_hi : g_dst_hi) + (((long)(b*HQ + hh))*Nq + n0)*DQ;
    uint32_t* ol = ((tid < 64) ? g_src_lo : g_dst_lo) + (((long)(b*HQ + hh))*Nq + n0)*DQ;
#pragma unroll
    for (int r = 0; r < 16; r++) {
        float v = sacc[r];
        uint32_t hi = f2tf(v);
        oh[r*DQ + d] = hi;
        ol[r*DQ + d] = f2tf(v - __uint_as_float(hi));
    }
}

// -------------------------------------------------------------------------
// K3: raw scores = attn_src @ attn_dst^T via 3xTF32, conversion-free.
// 64x64 tile, K chunked by 32. 8 warps in 4x2; warp tile 16x32.
// -------------------------------------------------------------------------
#define K3S 36
__global__ __launch_bounds__(256) void k3_scores() {
    __shared__ uint32_t Ah[64*K3S], Al[64*K3S], Bh[64*K3S], Bl[64*K3S];

    const int m0 = blockIdx.x * 64;   // cols (dst)
    const int n0 = blockIdx.y * 64;   // rows (src)
    const int bh = blockIdx.z;
    const int tid = threadIdx.x;
    const int warp = tid >> 5, lane = tid & 31;
    const int wr = warp >> 1;         // row offset *16
    const int wc = warp & 1;          // col offset *32
    const int qr = lane >> 2, qk = lane & 3;

    float C[4][4];
#pragma unroll
    for (int i = 0; i < 4; i++)
#pragma unroll
        for (int j = 0; j < 4; j++) C[i][j] = 0.f;

    const long srcb = ((long)bh*Nq + n0)*DQ;
    const long dstb = ((long)bh*Nq + m0)*DQ;

#pragma unroll
    for (int ch = 0; ch < 2; ch++) {
        if (ch) __syncthreads();
        const int kg = ch*32;
        // 64 rows x 32 words per array; uint4 vectors: 512 per array, 2/thread
#pragma unroll
        for (int t = 0; t < 2; t++) {
            int j = tid + t*256;
            int r = j >> 3, c = (j & 7) * 4;
            *(uint4*)&Ah[r*K3S + c] = *(const uint4*)&g_src_hi[srcb + r*DQ + kg + c];
            *(uint4*)&Al[r*K3S + c] = *(const uint4*)&g_src_lo[srcb + r*DQ + kg + c];
            *(uint4*)&Bh[r*K3S + c] = *(const uint4*)&g_dst_hi[dstb + r*DQ + kg + c];
            *(uint4*)&Bl[r*K3S + c] = *(const uint4*)&g_dst_lo[dstb + r*DQ + kg + c];
        }
        __syncthreads();

#pragma unroll
        for (int kk = 0; kk < 4; kk++) {
            const int k0 = kk*8;
            const uint32_t* aph = &Ah[(wr*16 + qr)*K3S + k0 + qk];
            const uint32_t* apl = &Al[(wr*16 + qr)*K3S + k0 + qk];
            uint32_t ah0 = aph[0], ah1 = aph[8*K3S], ah2 = aph[4], ah3 = aph[8*K3S + 4];
            uint32_t al0 = apl[0], al1 = apl[8*K3S], al2 = apl[4], al3 = apl[8*K3S + 4];
#pragma unroll
            for (int ct = 0; ct < 4; ct++) {
                const uint32_t* bph = &Bh[(wc*32 + ct*8 + qr)*K3S + k0 + qk];
                const uint32_t* bpl = &Bl[(wc*32 + ct*8 + qr)*K3S + k0 + qk];
                uint32_t bh0 = bph[0], bh1 = bph[4];
                uint32_t bl0 = bpl[0], bl1 = bpl[4];
                mma8(C[ct], ah0, ah1, ah2, ah3, bh0, bh1);
                mma8(C[ct], al0, al1, al2, al3, bh0, bh1);
                mma8(C[ct], ah0, ah1, ah2, ah3, bl0, bl1);
            }
        }
    }

    float* op = g_sc + ((size_t)bh*Nq + n0 + wr*16 + qr)*Nq + m0 + wc*32 + qk*2;
#pragma unroll
    for (int ct = 0; ct < 4; ct++) {
        *(float2*)&op[ct*8]                = make_float2(C[ct][0], C[ct][1]);
        *(float2*)&op[(size_t)8*Nq + ct*8] = make_float2(C[ct][2], C[ct][3]);
    }
}

// -------------------------------------------------------------------------
// K3b: leaky-relu + softmax + mask. One warp per row.
// -------------------------------------------------------------------------
__global__ __launch_bounds__(256) void k3b_softmax(const float* __restrict__ mask,
                                                   float* __restrict__ attn_out) {
    const int warp = threadIdx.x >> 5, lane = threadIdx.x & 31;
    const long row = (long)blockIdx.x*8 + warp;
    const int n  = (int)(row & (Nq - 1));
    const int bh = (int)(row >> 10);
    const int b  = bh >> 2;

    const float4* sp = (const float4*)(g_sc + (size_t)row*Nq);
    float4 v[8];
    float mx = -3.4e38f;
#pragma unroll
    for (int t = 0; t < 8; t++) {
        float4 x = sp[lane + t*32];
        x.x = x.x > 0.f ? x.x : NEG_SLOPE*x.x;
        x.y = x.y > 0.f ? x.y : NEG_SLOPE*x.y;
        x.z = x.z > 0.f ? x.z : NEG_SLOPE*x.z;
        x.w = x.w > 0.f ? x.w : NEG_SLOPE*x.w;
        v[t] = x;
        mx = fmaxf(mx, fmaxf(fmaxf(x.x, x.y), fmaxf(x.z, x.w)));
    }
#pragma unroll
    for (int o = 16; o; o >>= 1) mx = fmaxf(mx, __shfl_xor_sync(0xffffffffu, mx, o));
    float sum = 0.f;
#pragma unroll
    for (int t = 0; t < 8; t++) {
        v[t].x = __expf(v[t].x - mx);
        v[t].y = __expf(v[t].y - mx);
        v[t].z = __expf(v[t].z - mx);
        v[t].w = __expf(v[t].w - mx);
        sum += (v[t].x + v[t].y) + (v[t].z + v[t].w);
    }
#pragma unroll
    for (int o = 16; o; o >>= 1) sum += __shfl_xor_sync(0xffffffffu, sum, o);
    const float inv = 1.f / sum;

    const float4* mp = (const float4*)(mask + ((long)b*Nq + n)*Nq);
    float4* op = (float4*)(attn_out + (size_t)row*Nq);
#pragma unroll
    for (int t = 0; t < 8; t++) {
        float4 m = mp[lane + t*32];
        float4 x = v[t];
        op[lane + t*32] = make_float4(x.x*inv*m.x, x.y*inv*m.y, x.z*inv*m.z, x.w*inv*m.w);
    }
}

// -------------------------------------------------------------------------
// K4: out = sum_h attn @ h_prime + bias + sum_h h_prime.
// A (attn) in single tf32 (converted at smem fill); B (hp) precomputed hi/lo.
// 2 MMAs per tile. Block 64x128, k-chunk 32. 8 warps in 2x4; warp 32x32.
// -------------------------------------------------------------------------
#define A4S 36
#define B4S 136
__global__ __launch_bounds__(256) void k4_pv(const float* __restrict__ bias,
                                             const float* __restrict__ attn,
                                             float* __restrict__ out) {
    __shared__ uint32_t As[64*A4S];    // attn tf32-hi [64 rows][32 k]
    __shared__ uint32_t Bh4[32*B4S];   // hp hi [32 k][128 cols]
    __shared__ uint32_t Bl4[32*B4S];   // hp lo

    const int b  = blockIdx.y;
    const int n0 = blockIdx.x * 64;
    const int tid = threadIdx.x;
    const int warp = tid >> 5, lane = tid & 31;
    const int wr = warp >> 2;          // row offset *32
    const int wc = warp & 3;           // col offset *32
    const int qr = lane >> 2, qk = lane & 3;

    float C[2][4][4];
#pragma unroll
    for (int i = 0; i < 2; i++)
#pragma unroll
        for (int j = 0; j < 4; j++)
#pragma unroll
            for (int k = 0; k < 4; k++) C[i][j][k] = 0.f;

    for (int hh = 0; hh < HQ; hh++) {
        const float* ab = attn + (((size_t)(b*HQ + hh))*Nq + n0)*Nq;
        const long hbase = ((long)(b*HQ + hh))*Nq*FOUT;
        for (int kt = 0; kt < Nq/32; kt++) {
            __syncthreads();
            // A: 64 rows x 32 k floats -> tf32, 2048 words, 8/thread (2 f4)
#pragma unroll
            for (int t = 0; t < 2; t++) {
                int j = tid + t*256;
                int r = j >> 3, c = (j & 7) * 4;
                float4 x = *(const float4*)&ab[(size_t)r*Nq + kt*32 + c];
                uint4 y = make_uint4(f2tf(x.x), f2tf(x.y), f2tf(x.z), f2tf(x.w));
                *(uint4*)&As[r*A4S + c] = y;
            }
            // B: 32 k x 128 cols, 4096 words each, 16/thread (4 u4)
#pragma unroll
            for (int t = 0; t < 4; t++) {
                int j = tid + t*256;
                int r = j >> 5, c = (j & 31) * 4;
                const long gidx = hbase + (long)(kt*32 + r)*FOUT + c;
                *(uint4*)&Bh4[r*B4S + c] = *(const uint4*)&g_hp_hi[gidx];
                *(uint4*)&Bl4[r*B4S + c] = *(const uint4*)&g_hp_lo[gidx];
            }
            __syncthreads();
#pragma unroll
            for (int kk = 0; kk < 4; kk++) {
                const int k0 = kk*8;
                uint32_t AH[2][4];
#pragma unroll
                for (int rt = 0; rt < 2; rt++) {
                    const uint32_t* apt = &As[(wr*32 + rt*16 + qr)*A4S + k0 + qk];
                    AH[rt][0] = apt[0]; AH[rt][1] = apt[8*A4S];
                    AH[rt][2] = apt[4]; AH[rt][3] = apt[8*A4S + 4];
                }
#pragma unroll
                for (int ct = 0; ct < 4; ct++) {
                    const uint32_t* bph = &Bh4[(k0 + qk)*B4S + wc*32 + ct*8 + qr];
                    const uint32_t* bpl = &Bl4[(k0 + qk)*B4S + wc*32 + ct*8 + qr];
                    uint32_t bh0 = bph[0], bh1 = bph[4*B4S];
                    uint32_t bl0 = bpl[0], bl1 = bpl[4*B4S];
#pragma unroll
                    for (int rt = 0; rt < 2; rt++) {
                        mma8(C[rt][ct], AH[rt][0], AH[rt][1], AH[rt][2], AH[rt][3], bh0, bh1);
                        mma8(C[rt][ct], AH[rt][0], AH[rt][1], AH[rt][2], AH[rt][3], bl0, bl1);
                    }
                }
            }
        }
    }

    // epilogue: bias + skip (sum over heads of h_prime)
#pragma unroll
    for (int rt = 0; rt < 2; rt++) {
#pragma unroll
        for (int ct = 0; ct < 4; ct++) {
            int row = n0 + wr*32 + rt*16 + qr;
            int col = wc*32 + ct*8 + qk*2;
            float2 sk0 = make_float2(0.f, 0.f), sk1 = make_float2(0.f, 0.f);
#pragma unroll
            for (int hh = 0; hh < HQ; hh++) {
                const float* hb = g_hp + ((long)(b*HQ + hh))*Nq*FOUT;
                float2 x0 = *(const float2*)&hb[(long)row*FOUT + col];
                float2 x1 = *(const float2*)&hb[(long)(row + 8)*FOUT + col];
                sk0.x += x0.x; sk0.y += x0.y;
                sk1.x += x1.x; sk1.y += x1.y;
            }
            float2 bi = *(const float2*)&bias[col];
            *(float2*)&out[((long)b*Nq + row)*FOUT + col] =
                make_float2(C[rt][ct][0] + bi.x + sk0.x, C[rt][ct][1] + bi.y + sk0.y);
            *(float2*)&out[((long)b*Nq + row + 8)*FOUT + col] =
                make_float2(C[rt][ct][2] + bi.x + sk1.x, C[rt][ct][3] + bi.y + sk1.y);
        }
    }
}

extern "C" void kernel_launch(void* const* d_in, const int* in_sizes, int n_in,
                              void* d_out, int out_size) {
    const float* h     = (const float*)d_in[0];
    const float* mask  = (const float*)d_in[1];
    const float* w     = (const float*)d_in[2];
    const float* a_src = (const float*)d_in[3];
    const float* a_dst = (const float*)d_in[4];
    const float* bias  = (const float*)d_in[5];

    float* out      = (float*)d_out;               // [B,N,128]
    float* attn_out = (float*)d_out + OUT_ELEMS;   // [B,H,N,N]

    k1_hprime_proj<<<dim3(Nq/16, HQ, Bq), 128>>>(h, w, a_src, a_dst);
    k3_scores<<<dim3(Nq/64, Nq/64, Bq*HQ), 256>>>();
    k3b_softmax<<<(Bq*HQ*Nq)/8, 256>>>(mask, attn_out);
    k4_pv<<<dim3(Nq/64, Bq), 256>>>(bias, attn_out, out);
}

// round 5
// speedup vs baseline: 2.5386x; 1.3231x over previous
#include <cuda_runtime.h>
#include <cuda_bf16.h>
#include <cstdint>

#define Bq 16
#define Nq 1024
#define FIN 64
#define FOUT 128
#define DQ 64
#define HQ 4
#define NEG_SLOPE 0.2f

#define OUT_ELEMS (Bq*Nq*FOUT)          // 2097152
#define NROWS (Bq*HQ*Nq)                // 65536 attention rows

// Scratch (static device globals — allowed; no runtime allocation)
__device__ float    g_hp[Bq*HQ*Nq*FOUT];        // h_prime fp32 (skip epilogue)
__device__ uint32_t g_hp_hi[Bq*HQ*Nq*FOUT];     // h_prime tf32 (rna)
__device__ uint32_t g_src_hi[Bq*HQ*Nq*DQ];
__device__ uint32_t g_src_lo[Bq*HQ*Nq*DQ];
__device__ uint32_t g_dst_hi[Bq*HQ*Nq*DQ];
__device__ uint32_t g_dst_lo[Bq*HQ*Nq*DQ];
__device__ float    g_sc[(size_t)NROWS*Nq];     // post-leaky scores [B,H,N,N]
__device__ float2   g_part[(size_t)NROWS*32];   // per-(row, 32-col half) (max, sumexp)
__device__ float2   g_stat[NROWS];              // per-row (max, 1/sum)

// ---------------- helpers ----------------
__device__ __forceinline__ uint32_t f2tf(float f) {
    uint32_t r; asm("cvt.rna.tf32.f32 %0, %1;" : "=r"(r) : "f"(f)); return r;
}
__device__ __forceinline__ void mma8(float* c,
                                     uint32_t a0, uint32_t a1, uint32_t a2, uint32_t a3,
                                     uint32_t b0, uint32_t b1) {
    asm("mma.sync.aligned.m16n8k8.row.col.f32.tf32.tf32.f32 "
        "{%0,%1,%2,%3}, {%4,%5,%6,%7}, {%8,%9}, {%0,%1,%2,%3};"
        : "+f"(c[0]), "+f"(c[1]), "+f"(c[2]), "+f"(c[3])
        : "r"(a0), "r"(a1), "r"(a2), "r"(a3), "r"(b0), "r"(b1));
}
__device__ __forceinline__ void cpasync16(void* smem, const void* gmem) {
    uint32_t s = (uint32_t)__cvta_generic_to_shared(smem);
    asm volatile("cp.async.ca.shared.global [%0], [%1], 16;\n" :: "r"(s), "l"(gmem));
}
__device__ __forceinline__ void cpcommit() { asm volatile("cp.async.commit_group;\n"); }
__device__ __forceinline__ void cpwait0()  { asm volatile("cp.async.wait_group 0;\n"); }

// -------------------------------------------------------------------------
// K1: h_prime = h @ w[h]; attn_src/dst = h_prime @ a_src/a_dst.
// Emits fp32 h_prime + tf32 h_prime, and tf32 hi/lo of attn_src/attn_dst.
// -------------------------------------------------------------------------
__global__ void k1_hprime_proj(const float* __restrict__ h,
                               const float* __restrict__ w,
                               const float* __restrict__ a_src,
                               const float* __restrict__ a_dst) {
    __shared__ float h_s[16*FIN];
    __shared__ float w_s[FIN*FOUT];

    const int hh = blockIdx.y;
    const int b  = blockIdx.z;
    const int n0 = blockIdx.x * 16;
    const int tid = threadIdx.x;        // 128

    const float* hrow = h + ((long)b*Nq + n0)*FIN;
    for (int i = tid; i < 16*FIN; i += 128) h_s[i] = hrow[i];
    const float* wp = w + hh*FIN*FOUT;
    for (int i = tid; i < FIN*FOUT; i += 128) w_s[i] = wp[i];
    __syncthreads();

    float acc[16];
#pragma unroll
    for (int r = 0; r < 16; r++) acc[r] = 0.f;
#pragma unroll
    for (int f = 0; f < FIN; f++) {
        float wv = w_s[f*FOUT + tid];
#pragma unroll
        for (int r = 0; r < 16; r++) acc[r] += h_s[r*FIN + f] * wv;
    }

    const long hbase = (((long)(b*HQ + hh))*Nq + n0)*FOUT;
#pragma unroll
    for (int r = 0; r < 16; r++) {
        float v = acc[r];
        g_hp[hbase + r*FOUT + tid]    = v;
        g_hp_hi[hbase + r*FOUT + tid] = f2tf(v);
    }

    __syncthreads();
#pragma unroll
    for (int r = 0; r < 16; r++) w_s[r*FOUT + tid] = acc[r];
    __syncthreads();

    const int d = tid & 63;
    const float* ap = ((tid < 64) ? a_src : a_dst) + hh*FOUT*DQ;
    float sacc[16];
#pragma unroll
    for (int r = 0; r < 16; r++) sacc[r] = 0.f;
    for (int o = 0; o < FOUT; o++) {
        float av = ap[o*DQ + d];
#pragma unroll
        for (int r = 0; r < 16; r++) sacc[r] += w_s[r*FOUT + o] * av;
    }
    uint32_t* oh = ((tid < 64) ? g_src_hi : g_dst_hi) + (((long)(b*HQ + hh))*Nq + n0)*DQ;
    uint32_t* ol = ((tid < 64) ? g_src_lo : g_dst_lo) + (((long)(b*HQ + hh))*Nq + n0)*DQ;
#pragma unroll
    for (int r = 0; r < 16; r++) {
        float v = sacc[r];
        uint32_t hi = f2tf(v);
        oh[r*DQ + d] = hi;
        ol[r*DQ + d] = f2tf(v - __uint_as_float(hi));
    }
}

// -------------------------------------------------------------------------
// K3: scores = leaky(attn_src @ attn_dst^T) via 3xTF32 + per-tile softmax
// partial stats. 64x64 tile; 8 warps in 4x2; warp tile 16x32.
// -------------------------------------------------------------------------
#define K3S 36
__global__ __launch_bounds__(256) void k3_scores() {
    __shared__ uint32_t Ah[64*K3S], Al[64*K3S], Bh[64*K3S], Bl[64*K3S];

    const int m0 = blockIdx.x * 64;   // cols (dst index m)
    const int n0 = blockIdx.y * 64;   // rows (src index n)
    const int bh = blockIdx.z;
    const int tid = threadIdx.x;
    const int warp = tid >> 5, lane = tid & 31;
    const int wr = warp >> 1;         // row offset *16
    const int wc = warp & 1;          // col offset *32
    const int qr = lane >> 2, qk = lane & 3;

    float C[4][4];
#pragma unroll
    for (int i = 0; i < 4; i++)
#pragma unroll
        for (int j = 0; j < 4; j++) C[i][j] = 0.f;

    const long srcb = ((long)bh*Nq + n0)*DQ;
    const long dstb = ((long)bh*Nq + m0)*DQ;

#pragma unroll
    for (int ch = 0; ch < 2; ch++) {
        if (ch) __syncthreads();
        const int kg = ch*32;
#pragma unroll
        for (int t = 0; t < 2; t++) {
            int j = tid + t*256;
            int r = j >> 3, c = (j & 7) * 4;
            *(uint4*)&Ah[r*K3S + c] = *(const uint4*)&g_src_hi[srcb + r*DQ + kg + c];
            *(uint4*)&Al[r*K3S + c] = *(const uint4*)&g_src_lo[srcb + r*DQ + kg + c];
            *(uint4*)&Bh[r*K3S + c] = *(const uint4*)&g_dst_hi[dstb + r*DQ + kg + c];
            *(uint4*)&Bl[r*K3S + c] = *(const uint4*)&g_dst_lo[dstb + r*DQ + kg + c];
        }
        __syncthreads();

#pragma unroll
        for (int kk = 0; kk < 4; kk++) {
            const int k0 = kk*8;
            const uint32_t* aph = &Ah[(wr*16 + qr)*K3S + k0 + qk];
            const uint32_t* apl = &Al[(wr*16 + qr)*K3S + k0 + qk];
            uint32_t ah0 = aph[0], ah1 = aph[8*K3S], ah2 = aph[4], ah3 = aph[8*K3S + 4];
            uint32_t al0 = apl[0], al1 = apl[8*K3S], al2 = apl[4], al3 = apl[8*K3S + 4];
#pragma unroll
            for (int ct = 0; ct < 4; ct++) {
                const uint32_t* bph = &Bh[(wc*32 + ct*8 + qr)*K3S + k0 + qk];
                const uint32_t* bpl = &Bl[(wc*32 + ct*8 + qr)*K3S + k0 + qk];
                uint32_t b0 = bph[0], b1 = bph[4];
                uint32_t l0 = bpl[0], l1 = bpl[4];
                mma8(C[ct], ah0, ah1, ah2, ah3, b0, b1);
                mma8(C[ct], al0, al1, al2, al3, b0, b1);
                mma8(C[ct], ah0, ah1, ah2, ah3, l0, l1);
            }
        }
    }

    // leaky-relu in place
#pragma unroll
    for (int ct = 0; ct < 4; ct++)
#pragma unroll
        for (int i = 0; i < 4; i++) {
            float s = C[ct][i];
            C[ct][i] = s > 0.f ? s : NEG_SLOPE*s;
        }

    // store post-leaky scores
    float* op = g_sc + ((size_t)bh*Nq + n0 + wr*16 + qr)*Nq + m0 + wc*32 + qk*2;
#pragma unroll
    for (int ct = 0; ct < 4; ct++) {
        *(float2*)&op[ct*8]                = make_float2(C[ct][0], C[ct][1]);
        *(float2*)&op[(size_t)8*Nq + ct*8] = make_float2(C[ct][2], C[ct][3]);
    }

    // partial softmax stats per (row, 32-col half)
    const int halfidx = blockIdx.x*2 + wc;
    const size_t row0 = (size_t)bh*Nq + n0 + wr*16 + qr;
    {   // half 0: rows wr*16+qr (C[ct][0..1])
        float mx = fmaxf(fmaxf(fmaxf(C[0][0], C[0][1]), fmaxf(C[1][0], C[1][1])),
                         fmaxf(fmaxf(C[2][0], C[2][1]), fmaxf(C[3][0], C[3][1])));
        mx = fmaxf(mx, __shfl_xor_sync(0xffffffffu, mx, 1));
        mx = fmaxf(mx, __shfl_xor_sync(0xffffffffu, mx, 2));
        float s = 0.f;
#pragma unroll
        for (int ct = 0; ct < 4; ct++)
            s += __expf(C[ct][0] - mx) + __expf(C[ct][1] - mx);
        s += __shfl_xor_sync(0xffffffffu, s, 1);
        s += __shfl_xor_sync(0xffffffffu, s, 2);
        if (qk == 0) g_part[row0*32 + halfidx] = make_float2(mx, s);
    }
    {   // half 1: rows wr*16+qr+8 (C[ct][2..3])
        float mx = fmaxf(fmaxf(fmaxf(C[0][2], C[0][3]), fmaxf(C[1][2], C[1][3])),
                         fmaxf(fmaxf(C[2][2], C[2][3]), fmaxf(C[3][2], C[3][3])));
        mx = fmaxf(mx, __shfl_xor_sync(0xffffffffu, mx, 1));
        mx = fmaxf(mx, __shfl_xor_sync(0xffffffffu, mx, 2));
        float s = 0.f;
#pragma unroll
        for (int ct = 0; ct < 4; ct++)
            s += __expf(C[ct][2] - mx) + __expf(C[ct][3] - mx);
        s += __shfl_xor_sync(0xffffffffu, s, 1);
        s += __shfl_xor_sync(0xffffffffu, s, 2);
        if (qk == 0) g_part[(row0 + 8)*32 + halfidx] = make_float2(mx, s);
    }
}

// -------------------------------------------------------------------------
// K3r: reduce 32 partials per row -> (max, 1/sum). One warp per row.
// -------------------------------------------------------------------------
__global__ __launch_bounds__(256) void k3r_reduce() {
    const int warp = threadIdx.x >> 5, lane = threadIdx.x & 31;
    const size_t row = (size_t)blockIdx.x*8 + warp;
    float2 p = g_part[row*32 + lane];
    float M = p.x;
#pragma unroll
    for (int o = 16; o; o >>= 1) M = fmaxf(M, __shfl_xor_sync(0xffffffffu, M, o));
    float s = p.y * __expf(p.x - M);
#pragma unroll
    for (int o = 16; o; o >>= 1) s += __shfl_xor_sync(0xffffffffu, s, o);
    if (lane == 0) g_stat[row] = make_float2(M, 1.f / s);
}

// -------------------------------------------------------------------------
// K4: fused exp/mask/attn-write + PV GEMM (pipelined).
// Block 64 rows x 128 cols; 128 iters (4 heads x 32 k-tiles of 32).
// A built on the fly (exp(l-M)*inv*mask -> attn out + tf32 smem);
// B (hp tf32) via cp.async double buffer. 8 warps 2x4; warp 32x32.
// -------------------------------------------------------------------------
#define A4S 36
#define B4S 132
__global__ __launch_bounds__(256, 2) void k4_pv(const float* __restrict__ mask,
                                                const float* __restrict__ bias,
                                                float* __restrict__ attn_out,
                                                float* __restrict__ out) {
    __shared__ uint32_t As[64*A4S];        // attn tf32 [64 rows][32 k]
    __shared__ uint32_t Bs[2][32*B4S];     // hp tf32 double buffer
    __shared__ float2   sStat[HQ*64];      // per-head row stats

    const int b  = blockIdx.y;
    const int n0 = blockIdx.x * 64;
    const int tid = threadIdx.x;
    const int warp = tid >> 5, lane = tid & 31;
    const int wr = warp >> 2;          // row offset *32
    const int wc = warp & 3;           // col offset *32
    const int qr = lane >> 2, qk = lane & 3;

    // load per-head row stats (4 heads x 64 rows = 256 float2)
    {
        int hh = tid >> 6, r = tid & 63;
        sStat[tid] = g_stat[(size_t)(b*HQ + hh)*Nq + n0 + r];
    }

    float C[2][4][4];
#pragma unroll
    for (int i = 0; i < 2; i++)
#pragma unroll
        for (int j = 0; j < 4; j++)
#pragma unroll
            for (int k = 0; k < 4; k++) C[i][j][k] = 0.f;

    // thread's A/mask element coords (two vectors of 4)
    const int ar0 = tid >> 3,         ac0 = (tid & 7) * 4;          // j = tid
    const int ar1 = (tid + 256) >> 3, ac1 = ((tid + 256) & 7) * 4;  // j = tid+256

    // prologue: B(0) cp.async + A/mask(0) prefetch
    {
        const uint32_t* hb = g_hp_hi + (size_t)(b*HQ)*Nq*FOUT;   // h=0, kt=0
#pragma unroll
        for (int t = 0; t < 4; t++) {
            int j = tid + t*256;
            int kr = j >> 5, c = (j & 31) * 4;
            cpasync16(&Bs[0][kr*B4S + c], &hb[(size_t)kr*FOUT + c]);
        }
        cpcommit();
    }
    float4 rA0, rA1, rM0, rM1;
    {
        const float* scb = g_sc + ((size_t)(b*HQ)*Nq + n0)*Nq;    // h=0, kt=0
        const float* mkb = mask + ((size_t)b*Nq + n0)*Nq;
        rA0 = *(const float4*)&scb[(size_t)ar0*Nq + ac0];
        rA1 = *(const float4*)&scb[(size_t)ar1*Nq + ac1];
        rM0 = *(const float4*)&mkb[(size_t)ar0*Nq + ac0];
        rM1 = *(const float4*)&mkb[(size_t)ar1*Nq + ac1];
    }

    for (int it = 0; it < HQ*32; it++) {
        const int hh = it >> 5, kt = it & 31, stage = it & 1;
        cpwait0();
        __syncthreads();   // MMA(it-1) done everywhere; B(it) visible

        // process A(it): exp, scale, mask -> attn out + tf32 smem
        {
            const size_t abase = ((size_t)(b*HQ + hh)*Nq + n0);
            float2 st0 = sStat[hh*64 + ar0];
            float2 st1 = sStat[hh*64 + ar1];
            float4 a0, a1;
            a0.x = __expf(rA0.x - st0.x) * st0.y * rM0.x;
            a0.y = __expf(rA0.y - st0.x) * st0.y * rM0.y;
            a0.z = __expf(rA0.z - st0.x) * st0.y * rM0.z;
            a0.w = __expf(rA0.w - st0.x) * st0.y * rM0.w;
            a1.x = __expf(rA1.x - st1.x) * st1.y * rM1.x;
            a1.y = __expf(rA1.y - st1.x) * st1.y * rM1.y;
            a1.z = __expf(rA1.z - st1.x) * st1.y * rM1.z;
            a1.w = __expf(rA1.w - st1.x) * st1.y * rM1.w;
            *(float4*)&attn_out[(abase + ar0)*Nq + kt*32 + ac0] = a0;
            *(float4*)&attn_out[(abase + ar1)*Nq + kt*32 + ac1] = a1;
            *(uint4*)&As[ar0*A4S + ac0] = make_uint4(f2tf(a0.x), f2tf(a0.y), f2tf(a0.z), f2tf(a0.w));
            *(uint4*)&As[ar1*A4S + ac1] = make_uint4(f2tf(a1.x), f2tf(a1.y), f2tf(a1.z), f2tf(a1.w));
        }
        __syncthreads();   // As(it) visible

        // issue next-stage loads (overlap with MMA)
        if (it + 1 < HQ*32) {
            const int nh = (it + 1) >> 5, nkt = (it + 1) & 31;
            const uint32_t* hb = g_hp_hi + (size_t)(b*HQ + nh)*Nq*FOUT + (size_t)nkt*32*FOUT;
#pragma unroll
            for (int t = 0; t < 4; t++) {
                int j = tid + t*256;
                int kr = j >> 5, c = (j & 31) * 4;
                cpasync16(&Bs[stage ^ 1][kr*B4S + c], &hb[(size_t)kr*FOUT + c]);
            }
            cpcommit();
            const float* scb = g_sc + ((size_t)(b*HQ + nh)*Nq + n0)*Nq + nkt*32;
            const float* mkb = mask + ((size_t)b*Nq + n0)*Nq + nkt*32;
            rA0 = *(const float4*)&scb[(size_t)ar0*Nq + ac0];
            rA1 = *(const float4*)&scb[(size_t)ar1*Nq + ac1];
            rM0 = *(const float4*)&mkb[(size_t)ar0*Nq + ac0];
            rM1 = *(const float4*)&mkb[(size_t)ar1*Nq + ac1];
        }

        // MMA(it)
#pragma unroll
        for (int kk = 0; kk < 4; kk++) {
            const int k0 = kk*8;
            uint32_t AH[2][4];
#pragma unroll
            for (int rt = 0; rt < 2; rt++) {
                const uint32_t* apt = &As[(wr*32 + rt*16 + qr)*A4S + k0 + qk];
                AH[rt][0] = apt[0]; AH[rt][1] = apt[8*A4S];
                AH[rt][2] = apt[4]; AH[rt][3] = apt[8*A4S + 4];
            }
#pragma unroll
            for (int ct = 0; ct < 4; ct++) {
                const uint32_t* bp = &Bs[stage][(k0 + qk)*B4S + wc*32 + ct*8 + qr];
                uint32_t b0 = bp[0], b1 = bp[4*B4S];
#pragma unroll
                for (int rt = 0; rt < 2; rt++)
                    mma8(C[rt][ct], AH[rt][0], AH[rt][1], AH[rt][2], AH[rt][3], b0, b1);
            }
        }
    }

    // epilogue: bias + skip (sum over heads of h_prime)
#pragma unroll
    for (int rt = 0; rt < 2; rt++) {
#pragma unroll
        for (int ct = 0; ct < 4; ct++) {
            int row = n0 + wr*32 + rt*16 + qr;
            int col = wc*32 + ct*8 + qk*2;
            float2 sk0 = make_float2(0.f, 0.f), sk1 = make_float2(0.f, 0.f);
#pragma unroll
            for (int hh = 0; hh < HQ; hh++) {
                const float* hb = g_hp + ((long)(b*HQ + hh))*Nq*FOUT;
                float2 x0 = *(const float2*)&hb[(long)row*FOUT + col];
                float2 x1 = *(const float2*)&hb[(long)(row + 8)*FOUT + col];
                sk0.x += x0.x; sk0.y += x0.y;
                sk1.x += x1.x; sk1.y += x1.y;
            }
            float2 bi = *(const float2*)&bias[col];
            *(float2*)&out[((long)b*Nq + row)*FOUT + col] =
                make_float2(C[rt][ct][0] + bi.x + sk0.x, C[rt][ct][1] + bi.y + sk0.y);
            *(float2*)&out[((long)b*Nq + row + 8)*FOUT + col] =
                make_float2(C[rt][ct][2] + bi.x + sk1.x, C[rt][ct][3] + bi.y + sk1.y);
        }
    }
}

extern "C" void kernel_launch(void* const* d_in, const int* in_sizes, int n_in,
                              void* d_out, int out_size) {
    const float* h     = (const float*)d_in[0];
    const float* mask  = (const float*)d_in[1];
    const float* w     = (const float*)d_in[2];
    const float* a_src = (const float*)d_in[3];
    const float* a_dst = (const float*)d_in[4];
    const float* bias  = (const float*)d_in[5];

    float* out      = (float*)d_out;               // [B,N,128]
    float* attn_out = (float*)d_out + OUT_ELEMS;   // [B,H,N,N]

    k1_hprime_proj<<<dim3(Nq/16, HQ, Bq), 128>>>(h, w, a_src, a_dst);
    k3_scores<<<dim3(Nq/64, Nq/64, Bq*HQ), 256>>>();
    k3r_reduce<<<NROWS/8, 256>>>();
    k4_pv<<<dim3(Nq/64, Bq), 256>>>(mask, bias, attn_out, out);
}